// round 2
// baseline (speedup 1.0000x reference)
#include <cuda_runtime.h>
#include <cstdint>

#define N_NODES 50000
#define N_EDGES 800000
#define E_TOT   (N_EDGES + N_NODES)
#define DIM     128
#define NUM_GRAPHS 512

// ---------------- scratch (static device globals; no allocation allowed) ----
__device__ __align__(16) float g_buf0[N_NODES * DIM];
__device__ __align__(16) float g_buf1[N_NODES * DIM];
__device__ __align__(16) float g_h   [N_NODES * DIM];
__device__ float    g_e   [E_TOT];
__device__ float    g_as  [N_NODES];
__device__ float    g_ad  [N_NODES];
__device__ float    g_esum[N_NODES];
__device__ unsigned g_emax[N_NODES];
__device__ int      g_src [E_TOT];
__device__ int      g_dst [E_TOT];

// order-preserving float<->uint encode for atomicMax over signed floats
__device__ __forceinline__ unsigned enc_f(float f) {
    unsigned u = __float_as_uint(f);
    return (u & 0x80000000u) ? ~u : (u | 0x80000000u);
}
__device__ __forceinline__ float dec_f(unsigned u) {
    u = (u & 0x80000000u) ? (u & 0x7FFFFFFFu) : ~u;
    return __uint_as_float(u);
}

// ---------------- kernels ---------------------------------------------------

__global__ void k_prep(const int* __restrict__ ei) {
    int i = blockIdx.x * blockDim.x + threadIdx.x;
    if (i >= E_TOT) return;
    if (i < N_EDGES) {
        g_src[i] = ei[i];
        g_dst[i] = ei[N_EDGES + i];
    } else {
        int n = i - N_EDGES;          // self loops
        g_src[i] = n;
        g_dst[i] = n;
    }
}

__global__ void k_zero(float* __restrict__ p, int n) {
    int i = blockIdx.x * blockDim.x + threadIdx.x;
    int stride = gridDim.x * blockDim.x;
    for (; i < n; i += stride) p[i] = 0.f;
}

__global__ void k_init_seg() {
    int i = blockIdx.x * blockDim.x + threadIdx.x;
    if (i < N_NODES) { g_esum[i] = 0.f; g_emax[i] = 0u; }
}

// h = x @ W^T (optionally leaky_relu(x,0.01) on input), fused attention dots:
// g_as[n] = h[n].a_src ; g_ad[n] = h[n].a_dst
// block: 256 thr, 8 warps; 64 rows/block; each warp 8 rows, each lane 4 cols.
__global__ void k_gemm(const float* __restrict__ x, const float* __restrict__ W,
                       const float* __restrict__ a_src, const float* __restrict__ a_dst,
                       int apply_act) {
    extern __shared__ float sm[];
    float* Wt = sm;                 // [128][129] = W transposed, padded
    float* xs = sm + 128 * 129;     // [64][128]
    int tid = threadIdx.x;

    for (int t = tid; t < DIM * DIM; t += 256) {
        int j = t >> 7, k = t & 127;
        Wt[k * 129 + j] = W[t];
    }
    int n0 = blockIdx.x * 64;
    for (int t = tid; t < 64 * DIM; t += 256) {
        int r = t >> 7, k = t & 127;
        int n = n0 + r;
        float v = (n < N_NODES) ? x[(size_t)n * DIM + k] : 0.f;
        if (apply_act) v = v > 0.f ? v : 0.01f * v;
        xs[t] = v;
    }
    __syncthreads();

    int warp = tid >> 5, lane = tid & 31;
    int r0 = warp * 8;
    float acc[8][4];
#pragma unroll
    for (int r = 0; r < 8; r++)
#pragma unroll
        for (int m = 0; m < 4; m++) acc[r][m] = 0.f;

#pragma unroll 4
    for (int k = 0; k < DIM; k++) {
        float xv[8];
#pragma unroll
        for (int r = 0; r < 8; r++) xv[r] = xs[(r0 + r) * DIM + k];
#pragma unroll
        for (int m = 0; m < 4; m++) {
            float wv = Wt[k * 129 + lane + 32 * m];
#pragma unroll
            for (int r = 0; r < 8; r++) acc[r][m] = fmaf(xv[r], wv, acc[r][m]);
        }
    }

    float a_s[4], a_d[4];
#pragma unroll
    for (int m = 0; m < 4; m++) { a_s[m] = a_src[lane + 32 * m]; a_d[m] = a_dst[lane + 32 * m]; }

#pragma unroll
    for (int r = 0; r < 8; r++) {
        int n = n0 + r0 + r;
        if (n >= N_NODES) break;
        float ps = 0.f, pd = 0.f;
#pragma unroll
        for (int m = 0; m < 4; m++) {
            ps += acc[r][m] * a_s[m];
            pd += acc[r][m] * a_d[m];
            g_h[(size_t)n * DIM + lane + 32 * m] = acc[r][m];
        }
#pragma unroll
        for (int o = 16; o > 0; o >>= 1) {
            ps += __shfl_xor_sync(0xffffffffu, ps, o);
            pd += __shfl_xor_sync(0xffffffffu, pd, o);
        }
        if (lane == 0) { g_as[n] = ps; g_ad[n] = pd; }
    }
}

// pass 1: e = leaky_relu(as[src]+ad[dst], 0.2); segment max over dst
__global__ void k_edge1() {
    int i = blockIdx.x * blockDim.x + threadIdx.x;
    if (i >= E_TOT) return;
    int s = g_src[i], d = g_dst[i];
    float e = g_as[s] + g_ad[d];
    e = e > 0.f ? e : 0.2f * e;
    g_e[i] = e;
    atomicMax(&g_emax[d], enc_f(e));
}

// pass 2: ee = exp(e - max); segment sum
__global__ void k_edge2() {
    int i = blockIdx.x * blockDim.x + threadIdx.x;
    if (i >= E_TOT) return;
    int d = g_dst[i];
    float ee = expf(g_e[i] - dec_f(g_emax[d]));
    g_e[i] = ee;
    atomicAdd(&g_esum[d], ee);
}

// pass 3: out[dst] += alpha * h[src]. One warp per edge, float4 per lane,
// vectorized global reductions.
__global__ void k_agg(float* __restrict__ out) {
    int gt = blockIdx.x * blockDim.x + threadIdx.x;
    int w = gt >> 5, lane = gt & 31;
    if (w >= E_TOT) return;
    int s = g_src[w], d = g_dst[w];
    float alpha = g_e[w] / (g_esum[d] + 1e-16f);
    float4 v = ((const float4*)(g_h + (size_t)s * DIM))[lane];
    v.x *= alpha; v.y *= alpha; v.z *= alpha; v.w *= alpha;
    float* p = out + (size_t)d * DIM + lane * 4;
    asm volatile("red.global.add.v4.f32 [%0], {%1,%2,%3,%4};"
                 :: "l"(p), "f"(v.x), "f"(v.y), "f"(v.z), "f"(v.w) : "memory");
}

// global add pool over batch
__global__ void k_pool(const float* __restrict__ xin, const int* __restrict__ batch,
                       float* __restrict__ out) {
    int t = blockIdx.x * blockDim.x + threadIdx.x;
    if (t >= N_NODES * 32) return;
    int n = t >> 5, c = t & 31;
    float4 v = ((const float4*)(xin + (size_t)n * DIM))[c];
    int b = batch[n];
    float* p = out + (size_t)b * DIM + c * 4;
    asm volatile("red.global.add.v4.f32 [%0], {%1,%2,%3,%4};"
                 :: "l"(p), "f"(v.x), "f"(v.y), "f"(v.z), "f"(v.w) : "memory");
}

// ---------------- launch ----------------------------------------------------

extern "C" void kernel_launch(void* const* d_in, const int* in_sizes, int n_in,
                              void* d_out, int out_size) {
    const float* x     = (const float*)d_in[0];
    const int*   ei    = (const int*)d_in[1];    // int32 (JAX x64 disabled)
    const int*   batch = (const int*)d_in[2];
    const float* W[3]  = {(const float*)d_in[3], (const float*)d_in[6], (const float*)d_in[9]};
    const float* As[3] = {(const float*)d_in[4], (const float*)d_in[7], (const float*)d_in[10]};
    const float* Ad[3] = {(const float*)d_in[5], (const float*)d_in[8], (const float*)d_in[11]};
    float* out = (float*)d_out;

    float *buf0, *buf1;
    cudaGetSymbolAddress((void**)&buf0, g_buf0);
    cudaGetSymbolAddress((void**)&buf1, g_buf1);

    const int SMEM_BYTES = (128 * 129 + 64 * 128) * (int)sizeof(float);
    cudaFuncSetAttribute(k_gemm, cudaFuncAttributeMaxDynamicSharedMemorySize, SMEM_BYTES);

    k_prep<<<(E_TOT + 255) / 256, 256>>>(ei);

    const float* cur = x;
    float* nxt = buf0;
    for (int l = 0; l < 3; l++) {
        k_zero<<<1024, 256>>>(nxt, N_NODES * DIM);
        k_init_seg<<<(N_NODES + 255) / 256, 256>>>();
        k_gemm<<<(N_NODES + 63) / 64, 256, SMEM_BYTES>>>(cur, W[l], As[l], Ad[l], l == 2 ? 1 : 0);
        k_edge1<<<(E_TOT + 255) / 256, 256>>>();
        k_edge2<<<(E_TOT + 255) / 256, 256>>>();
        k_agg<<<(E_TOT * 32 + 255) / 256, 256>>>(nxt);
        cur = nxt;
        nxt = (l == 0) ? buf1 : buf0;
    }

    k_zero<<<64, 256>>>(out, NUM_GRAPHS * DIM);
    k_pool<<<(N_NODES * 32 + 255) / 256, 256>>>(cur, batch, out);
}

// round 3
// speedup vs baseline: 1.5091x; 1.5091x over previous
#include <cuda_runtime.h>
#include <cstdint>

#define N_NODES 50000
#define N_EDGES 800000
#define E_TOT   (N_EDGES + N_NODES)
#define DIM     128
#define NUM_GRAPHS 512

// ---------------- scratch -------------------------------------------------
__device__ __align__(16) float g_buf0[N_NODES * DIM];
__device__ __align__(16) float g_buf1[N_NODES * DIM];
__device__ __align__(16) float g_h   [N_NODES * DIM];
__device__ float g_as  [N_NODES];
__device__ float g_ad  [N_NODES];
__device__ int   g_src [E_TOT];
__device__ int   g_dst [E_TOT];
__device__ int   g_cnt [N_NODES];
__device__ int   g_cur [N_NODES];
__device__ int   g_row [N_NODES + 1];
__device__ int   g_csrs[E_TOT];

// ---------------- CSR build ----------------------------------------------
__global__ void k_zero_cnt() {
    int i = blockIdx.x * blockDim.x + threadIdx.x;
    if (i < N_NODES) g_cnt[i] = 0;
}

__global__ void k_prep_count(const int* __restrict__ ei) {
    int i = blockIdx.x * blockDim.x + threadIdx.x;
    if (i >= E_TOT) return;
    int s, d;
    if (i < N_EDGES) { s = ei[i]; d = ei[N_EDGES + i]; }
    else             { s = i - N_EDGES; d = s; }        // self loops
    g_src[i] = s;
    g_dst[i] = d;
    atomicAdd(&g_cnt[d], 1);
}

__global__ void k_scan() {          // single block, 1024 threads
    const int T = 1024;
    const int C = (N_NODES + T - 1) / T;   // 49
    __shared__ int ps[T];
    int t = threadIdx.x;
    int base = t * C;
    int s = 0;
    for (int i = 0; i < C; i++) { int n = base + i; if (n < N_NODES) s += g_cnt[n]; }
    ps[t] = s;
    __syncthreads();
    for (int off = 1; off < T; off <<= 1) {
        int v = (t >= off) ? ps[t - off] : 0;
        __syncthreads();
        ps[t] += v;
        __syncthreads();
    }
    int run = (t > 0) ? ps[t - 1] : 0;
    for (int i = 0; i < C; i++) {
        int n = base + i;
        if (n < N_NODES) { g_row[n] = run; g_cur[n] = run; run += g_cnt[n]; }
    }
    if (t == T - 1) g_row[N_NODES] = E_TOT;
}

__global__ void k_fill() {
    int i = blockIdx.x * blockDim.x + threadIdx.x;
    if (i >= E_TOT) return;
    int d = g_dst[i];
    int pos = atomicAdd(&g_cur[d], 1);
    g_csrs[pos] = g_src[i];
}

// ---------------- GEMM: h = act?(x) @ W^T, fused attention dots -----------
// 128x128x16 tiles, 256 threads, 8x8 per thread.
#define BK 16
#define SM_PAD 132

__global__ void __launch_bounds__(256, 2)
k_gemm(const float* __restrict__ x, const float* __restrict__ W,
       const float* __restrict__ a_src, const float* __restrict__ a_dst,
       int apply_act) {
    __shared__ float As[BK][SM_PAD];   // As[k][m] = x[n0+m][k]
    __shared__ float Bs[BK][SM_PAD];   // Bs[k][j] = W[j][k]
    int tid = threadIdx.x;
    int tx = tid & 15, ty = tid >> 4;          // 16x16
    int n0 = blockIdx.x * 128;

    int lr = tid >> 2;          // 0..63: row within tile (and row+64)
    int lq = tid & 3;           // float4 index within the 16-wide k slice

    float acc[8][8];
#pragma unroll
    for (int i = 0; i < 8; i++)
#pragma unroll
        for (int j = 0; j < 8; j++) acc[i][j] = 0.f;

    for (int k0 = 0; k0 < DIM; k0 += BK) {
        // load x tile (rows n0..n0+127, cols k0..k0+15), transpose to As
#pragma unroll
        for (int half = 0; half < 2; half++) {
            int r = lr + half * 64;
            int n = n0 + r;
            float4 v = make_float4(0.f, 0.f, 0.f, 0.f);
            if (n < N_NODES)
                v = *(const float4*)(x + (size_t)n * DIM + k0 + lq * 4);
            if (apply_act) {
                v.x = v.x > 0.f ? v.x : 0.01f * v.x;
                v.y = v.y > 0.f ? v.y : 0.01f * v.y;
                v.z = v.z > 0.f ? v.z : 0.01f * v.z;
                v.w = v.w > 0.f ? v.w : 0.01f * v.w;
            }
            As[lq * 4 + 0][r] = v.x;
            As[lq * 4 + 1][r] = v.y;
            As[lq * 4 + 2][r] = v.z;
            As[lq * 4 + 3][r] = v.w;
        }
        // load W tile (rows j=0..127, cols k0..k0+15), transpose to Bs
#pragma unroll
        for (int half = 0; half < 2; half++) {
            int j = lr + half * 64;
            float4 v = *(const float4*)(W + (size_t)j * DIM + k0 + lq * 4);
            Bs[lq * 4 + 0][j] = v.x;
            Bs[lq * 4 + 1][j] = v.y;
            Bs[lq * 4 + 2][j] = v.z;
            Bs[lq * 4 + 3][j] = v.w;
        }
        __syncthreads();

#pragma unroll
        for (int k = 0; k < BK; k++) {
            float4 a0 = *(const float4*)&As[k][ty * 8];
            float4 a1 = *(const float4*)&As[k][ty * 8 + 4];
            float4 b0 = *(const float4*)&Bs[k][tx * 8];
            float4 b1 = *(const float4*)&Bs[k][tx * 8 + 4];
            float av[8] = {a0.x, a0.y, a0.z, a0.w, a1.x, a1.y, a1.z, a1.w};
            float bv[8] = {b0.x, b0.y, b0.z, b0.w, b1.x, b1.y, b1.z, b1.w};
#pragma unroll
            for (int i = 0; i < 8; i++)
#pragma unroll
                for (int j = 0; j < 8; j++)
                    acc[i][j] = fmaf(av[i], bv[j], acc[i][j]);
        }
        __syncthreads();
    }

    // epilogue: write h rows, fused attention dots
    float a_s[8], a_d[8];
#pragma unroll
    for (int j = 0; j < 8; j++) { a_s[j] = a_src[tx * 8 + j]; a_d[j] = a_dst[tx * 8 + j]; }

#pragma unroll
    for (int i = 0; i < 8; i++) {
        int n = n0 + ty * 8 + i;
        float ps = 0.f, pd = 0.f;
#pragma unroll
        for (int j = 0; j < 8; j++) {
            ps = fmaf(acc[i][j], a_s[j], ps);
            pd = fmaf(acc[i][j], a_d[j], pd);
        }
#pragma unroll
        for (int o = 1; o < 16; o <<= 1) {
            ps += __shfl_xor_sync(0xffffffffu, ps, o);
            pd += __shfl_xor_sync(0xffffffffu, pd, o);
        }
        if (n < N_NODES) {
            *(float4*)(g_h + (size_t)n * DIM + tx * 8)     = make_float4(acc[i][0], acc[i][1], acc[i][2], acc[i][3]);
            *(float4*)(g_h + (size_t)n * DIM + tx * 8 + 4) = make_float4(acc[i][4], acc[i][5], acc[i][6], acc[i][7]);
            if (tx == 0) { g_as[n] = ps; g_ad[n] = pd; }
        }
    }
}

// ---------------- fused softmax + aggregate: one warp per dst node --------
__global__ void k_layer(float* __restrict__ outp, const int* __restrict__ batch,
                        int fuse_pool) {
    int gt = blockIdx.x * blockDim.x + threadIdx.x;
    int d = gt >> 5, lane = gt & 31;
    if (d >= N_NODES) return;
    int row0 = g_row[d], row1 = g_row[d + 1];
    float ad_d = g_ad[d];

    // pass 1: segment max (lanes split edges)
    float m = -1e30f;
    for (int i = row0 + lane; i < row1; i += 32) {
        float e = g_as[g_csrs[i]] + ad_d;
        e = e > 0.f ? e : 0.2f * e;
        m = fmaxf(m, e);
    }
#pragma unroll
    for (int o = 16; o > 0; o >>= 1)
        m = fmaxf(m, __shfl_xor_sync(0xffffffffu, m, o));

    // pass 2: z and weighted aggregate (lanes split dims, edges serial x2)
    float z = 0.f;
    float4 acc = make_float4(0.f, 0.f, 0.f, 0.f);
    int i = row0;
    for (; i + 2 <= row1; i += 2) {
        int s0 = g_csrs[i], s1 = g_csrs[i + 1];
        float e0 = g_as[s0] + ad_d; e0 = e0 > 0.f ? e0 : 0.2f * e0;
        float e1 = g_as[s1] + ad_d; e1 = e1 > 0.f ? e1 : 0.2f * e1;
        float w0 = __expf(e0 - m), w1 = __expf(e1 - m);
        z += w0 + w1;
        float4 h0 = ((const float4*)(g_h + (size_t)s0 * DIM))[lane];
        float4 h1 = ((const float4*)(g_h + (size_t)s1 * DIM))[lane];
        acc.x = fmaf(w0, h0.x, fmaf(w1, h1.x, acc.x));
        acc.y = fmaf(w0, h0.y, fmaf(w1, h1.y, acc.y));
        acc.z = fmaf(w0, h0.z, fmaf(w1, h1.z, acc.z));
        acc.w = fmaf(w0, h0.w, fmaf(w1, h1.w, acc.w));
    }
    if (i < row1) {
        int s0 = g_csrs[i];
        float e0 = g_as[s0] + ad_d; e0 = e0 > 0.f ? e0 : 0.2f * e0;
        float w0 = __expf(e0 - m);
        z += w0;
        float4 h0 = ((const float4*)(g_h + (size_t)s0 * DIM))[lane];
        acc.x = fmaf(w0, h0.x, acc.x);
        acc.y = fmaf(w0, h0.y, acc.y);
        acc.z = fmaf(w0, h0.z, acc.z);
        acc.w = fmaf(w0, h0.w, acc.w);
    }
    float inv = 1.f / (z + 1e-16f);
    acc.x *= inv; acc.y *= inv; acc.z *= inv; acc.w *= inv;

    if (fuse_pool) {
        float* p = outp + (size_t)batch[d] * DIM + lane * 4;
        asm volatile("red.global.add.v4.f32 [%0], {%1,%2,%3,%4};"
                     :: "l"(p), "f"(acc.x), "f"(acc.y), "f"(acc.z), "f"(acc.w) : "memory");
    } else {
        ((float4*)(outp + (size_t)d * DIM))[lane] = acc;
    }
}

__global__ void k_zero(float* __restrict__ p, int n) {
    int i = blockIdx.x * blockDim.x + threadIdx.x;
    if (i < n) p[i] = 0.f;
}

// ---------------- launch --------------------------------------------------
extern "C" void kernel_launch(void* const* d_in, const int* in_sizes, int n_in,
                              void* d_out, int out_size) {
    const float* x     = (const float*)d_in[0];
    const int*   ei    = (const int*)d_in[1];
    const int*   batch = (const int*)d_in[2];
    const float* W[3]  = {(const float*)d_in[3], (const float*)d_in[6], (const float*)d_in[9]};
    const float* As_[3] = {(const float*)d_in[4], (const float*)d_in[7], (const float*)d_in[10]};
    const float* Ad_[3] = {(const float*)d_in[5], (const float*)d_in[8], (const float*)d_in[11]};
    float* out = (float*)d_out;

    float *buf0, *buf1;
    cudaGetSymbolAddress((void**)&buf0, g_buf0);
    cudaGetSymbolAddress((void**)&buf1, g_buf1);

    // CSR build (per launch; capturable, no allocation)
    k_zero_cnt<<<(N_NODES + 255) / 256, 256>>>();
    k_prep_count<<<(E_TOT + 255) / 256, 256>>>(ei);
    k_scan<<<1, 1024>>>();
    k_fill<<<(E_TOT + 255) / 256, 256>>>();

    k_zero<<<(NUM_GRAPHS * DIM + 255) / 256, 256>>>(out, NUM_GRAPHS * DIM);

    const float* cur = x;
    float* bufs[3] = {buf0, buf1, nullptr};
    for (int l = 0; l < 3; l++) {
        k_gemm<<<(N_NODES + 127) / 128, 256>>>(cur, W[l], As_[l], Ad_[l], l == 2 ? 1 : 0);
        if (l < 2) {
            k_layer<<<(N_NODES * 32 + 255) / 256, 256>>>(bufs[l], batch, 0);
            cur = bufs[l];
        } else {
            k_layer<<<(N_NODES * 32 + 255) / 256, 256>>>(out, batch, 1);
        }
    }
}

// round 6
// speedup vs baseline: 1.5735x; 1.0427x over previous
#include <cuda_runtime.h>
#include <mma.h>
#include <cstdint>

using namespace nvcuda;

#define N_NODES 50000
#define NPAD    50048          // 391 * 128
#define N_EDGES 800000
#define E_TOT   (N_EDGES + N_NODES)
#define DIM     128
#define NUM_GRAPHS 512

// ---------------- scratch -------------------------------------------------
__device__ __align__(16) float g_x   [NPAD * DIM];   // padded copy of x
__device__ __align__(16) float g_buf0[NPAD * DIM];
__device__ __align__(16) float g_buf1[NPAD * DIM];
__device__ __align__(16) float g_h   [NPAD * DIM];
__device__ float g_as  [N_NODES];
__device__ float g_ad  [N_NODES];
__device__ int   g_src [E_TOT];
__device__ int   g_dst [E_TOT];
__device__ int   g_cnt [N_NODES];
__device__ int   g_cur [N_NODES];
__device__ int   g_row [N_NODES + 1];
__device__ int   g_csrs[E_TOT];

// ---------------- CSR build ----------------------------------------------
__global__ void k_zero_cnt() {
    int i = blockIdx.x * blockDim.x + threadIdx.x;
    if (i < N_NODES) g_cnt[i] = 0;
}

__global__ void k_prep_count(const int* __restrict__ ei) {
    int i = blockIdx.x * blockDim.x + threadIdx.x;
    if (i >= E_TOT) return;
    int s, d;
    if (i < N_EDGES) { s = ei[i]; d = ei[N_EDGES + i]; }
    else             { s = i - N_EDGES; d = s; }        // self loops
    g_src[i] = s;
    g_dst[i] = d;
    atomicAdd(&g_cnt[d], 1);
}

__global__ void k_scan() {          // single block, 1024 threads
    const int T = 1024;
    const int C = (N_NODES + T - 1) / T;
    __shared__ int ps[T];
    int t = threadIdx.x;
    int base = t * C;
    int s = 0;
    for (int i = 0; i < C; i++) { int n = base + i; if (n < N_NODES) s += g_cnt[n]; }
    ps[t] = s;
    __syncthreads();
    for (int off = 1; off < T; off <<= 1) {
        int v = (t >= off) ? ps[t - off] : 0;
        __syncthreads();
        ps[t] += v;
        __syncthreads();
    }
    int run = (t > 0) ? ps[t - 1] : 0;
    for (int i = 0; i < C; i++) {
        int n = base + i;
        if (n < N_NODES) { g_row[n] = run; g_cur[n] = run; run += g_cnt[n]; }
    }
    if (t == T - 1) g_row[N_NODES] = E_TOT;
}

__global__ void k_fill() {
    int i = blockIdx.x * blockDim.x + threadIdx.x;
    if (i >= E_TOT) return;
    int d = g_dst[i];
    int pos = atomicAdd(&g_cur[d], 1);
    g_csrs[pos] = g_src[i];
}

// ---------------- misc ----------------------------------------------------
__global__ void k_copy_x(const float* __restrict__ x) {
    int i = blockIdx.x * blockDim.x + threadIdx.x;
    if (i < N_NODES * (DIM / 4))
        ((float4*)g_x)[i] = ((const float4*)x)[i];
}

__global__ void k_zero(float* __restrict__ p, int n) {
    int i = blockIdx.x * blockDim.x + threadIdx.x;
    if (i < n) p[i] = 0.f;
}

// ---------------- tf32 tensor-core GEMM: H = act?(X) @ W^T ----------------
// 256 threads = 8 warps (4 x 2). Block tile 128x128, warp tile 32x64.
__global__ void __launch_bounds__(256)
k_gemm(const float* __restrict__ X, const float* __restrict__ W,
       float* __restrict__ H, int apply_act) {
    int warp = threadIdx.x >> 5;
    int wm = warp & 3, wn = warp >> 2;
    int row0 = blockIdx.x * 128 + wm * 32;
    int col0 = wn * 64;

    wmma::fragment<wmma::accumulator, 16, 16, 8, float> c[2][4];
#pragma unroll
    for (int i = 0; i < 2; i++)
#pragma unroll
        for (int j = 0; j < 4; j++) wmma::fill_fragment(c[i][j], 0.f);

#pragma unroll 4
    for (int k0 = 0; k0 < DIM; k0 += 8) {
        wmma::fragment<wmma::matrix_a, 16, 16, 8, wmma::precision::tf32, wmma::row_major> a[2];
        wmma::fragment<wmma::matrix_b, 16, 16, 8, wmma::precision::tf32, wmma::col_major> b[4];
#pragma unroll
        for (int i = 0; i < 2; i++) {
            wmma::load_matrix_sync(a[i], X + (size_t)(row0 + i * 16) * DIM + k0, DIM);
#pragma unroll
            for (int t = 0; t < a[i].num_elements; t++) {
                float v = a[i].x[t];
                if (apply_act) v = v > 0.f ? v : 0.01f * v;
                a[i].x[t] = wmma::__float_to_tf32(v);
            }
        }
#pragma unroll
        for (int j = 0; j < 4; j++) {
            // B[k][n] = W[n][k] -> col_major with ldm = DIM
            wmma::load_matrix_sync(b[j], W + (size_t)(col0 + j * 16) * DIM + k0, DIM);
#pragma unroll
            for (int t = 0; t < b[j].num_elements; t++)
                b[j].x[t] = wmma::__float_to_tf32(b[j].x[t]);
        }
#pragma unroll
        for (int i = 0; i < 2; i++)
#pragma unroll
            for (int j = 0; j < 4; j++)
                wmma::mma_sync(c[i][j], a[i], b[j], c[i][j]);
    }

#pragma unroll
    for (int i = 0; i < 2; i++)
#pragma unroll
        for (int j = 0; j < 4; j++)
            wmma::store_matrix_sync(H + (size_t)(row0 + i * 16) * DIM + col0 + j * 16,
                                    c[i][j], DIM, wmma::mem_row_major);
}

// ---------------- attention dots: as[n]=h_n.a_src, ad[n]=h_n.a_dst --------
__global__ void k_att_dot(const float* __restrict__ a_src, const float* __restrict__ a_dst) {
    int gt = blockIdx.x * blockDim.x + threadIdx.x;
    int n = gt >> 5, lane = gt & 31;
    if (n >= N_NODES) return;
    float4 h = ((const float4*)(g_h + (size_t)n * DIM))[lane];
    float4 as4 = ((const float4*)a_src)[lane];
    float4 ad4 = ((const float4*)a_dst)[lane];
    float ps = h.x * as4.x + h.y * as4.y + h.z * as4.z + h.w * as4.w;
    float pd = h.x * ad4.x + h.y * ad4.y + h.z * ad4.z + h.w * ad4.w;
#pragma unroll
    for (int o = 16; o > 0; o >>= 1) {
        ps += __shfl_xor_sync(0xffffffffu, ps, o);
        pd += __shfl_xor_sync(0xffffffffu, pd, o);
    }
    if (lane == 0) { g_as[n] = ps; g_ad[n] = pd; }
}

// ---------------- fused softmax + aggregate: one warp per dst node --------
__global__ void k_layer(float* __restrict__ outp, const int* __restrict__ batch,
                        int fuse_pool) {
    int gt = blockIdx.x * blockDim.x + threadIdx.x;
    int d = gt >> 5, lane = gt & 31;
    if (d >= N_NODES) return;
    int row0 = g_row[d], row1 = g_row[d + 1];
    float ad_d = g_ad[d];

    // pass 1: segment max (lanes split edges)
    float m = -1e30f;
    for (int i = row0 + lane; i < row1; i += 32) {
        float e = g_as[g_csrs[i]] + ad_d;
        e = e > 0.f ? e : 0.2f * e;
        m = fmaxf(m, e);
    }
#pragma unroll
    for (int o = 16; o > 0; o >>= 1)
        m = fmaxf(m, __shfl_xor_sync(0xffffffffu, m, o));

    // pass 2: z and weighted aggregate (lanes split dims)
    float z = 0.f;
    float4 acc = make_float4(0.f, 0.f, 0.f, 0.f);
    int i = row0;
    for (; i + 2 <= row1; i += 2) {
        int s0 = g_csrs[i], s1 = g_csrs[i + 1];
        float e0 = g_as[s0] + ad_d; e0 = e0 > 0.f ? e0 : 0.2f * e0;
        float e1 = g_as[s1] + ad_d; e1 = e1 > 0.f ? e1 : 0.2f * e1;
        float w0 = __expf(e0 - m), w1 = __expf(e1 - m);
        z += w0 + w1;
        float4 h0 = ((const float4*)(g_h + (size_t)s0 * DIM))[lane];
        float4 h1 = ((const float4*)(g_h + (size_t)s1 * DIM))[lane];
        acc.x = fmaf(w0, h0.x, fmaf(w1, h1.x, acc.x));
        acc.y = fmaf(w0, h0.y, fmaf(w1, h1.y, acc.y));
        acc.z = fmaf(w0, h0.z, fmaf(w1, h1.z, acc.z));
        acc.w = fmaf(w0, h0.w, fmaf(w1, h1.w, acc.w));
    }
    if (i < row1) {
        int s0 = g_csrs[i];
        float e0 = g_as[s0] + ad_d; e0 = e0 > 0.f ? e0 : 0.2f * e0;
        float w0 = __expf(e0 - m);
        z += w0;
        float4 h0 = ((const float4*)(g_h + (size_t)s0 * DIM))[lane];
        acc.x = fmaf(w0, h0.x, acc.x);
        acc.y = fmaf(w0, h0.y, acc.y);
        acc.z = fmaf(w0, h0.z, acc.z);
        acc.w = fmaf(w0, h0.w, acc.w);
    }
    float inv = 1.f / (z + 1e-16f);
    acc.x *= inv; acc.y *= inv; acc.z *= inv; acc.w *= inv;

    if (fuse_pool) {
        float* p = outp + (size_t)batch[d] * DIM + lane * 4;
        asm volatile("red.global.add.v4.f32 [%0], {%1,%2,%3,%4};"
                     :: "l"(p), "f"(acc.x), "f"(acc.y), "f"(acc.z), "f"(acc.w) : "memory");
    } else {
        ((float4*)(outp + (size_t)d * DIM))[lane] = acc;
    }
}

// ---------------- launch --------------------------------------------------
extern "C" void kernel_launch(void* const* d_in, const int* in_sizes, int n_in,
                              void* d_out, int out_size) {
    const float* x     = (const float*)d_in[0];
    const int*   ei    = (const int*)d_in[1];
    const int*   batch = (const int*)d_in[2];
    const float* W[3]   = {(const float*)d_in[3], (const float*)d_in[6], (const float*)d_in[9]};
    const float* As_[3] = {(const float*)d_in[4], (const float*)d_in[7], (const float*)d_in[10]};
    const float* Ad_[3] = {(const float*)d_in[5], (const float*)d_in[8], (const float*)d_in[11]};
    float* out = (float*)d_out;

    float *xp, *buf0, *buf1, *hp;
    cudaGetSymbolAddress((void**)&xp,   g_x);
    cudaGetSymbolAddress((void**)&buf0, g_buf0);
    cudaGetSymbolAddress((void**)&buf1, g_buf1);
    cudaGetSymbolAddress((void**)&hp,   g_h);

    // CSR build (per launch; capturable, no allocation)
    k_zero_cnt<<<(N_NODES + 255) / 256, 256>>>();
    k_prep_count<<<(E_TOT + 255) / 256, 256>>>(ei);
    k_scan<<<1, 1024>>>();
    k_fill<<<(E_TOT + 255) / 256, 256>>>();

    k_copy_x<<<(N_NODES * 32 + 255) / 256, 256>>>(x);
    k_zero<<<(NUM_GRAPHS * DIM + 255) / 256, 256>>>(out, NUM_GRAPHS * DIM);

    const float* cur = xp;
    float* bufs[2] = {buf0, buf1};
    for (int l = 0; l < 3; l++) {
        k_gemm<<<NPAD / 128, 256>>>(cur, W[l], hp, l == 2 ? 1 : 0);
        k_att_dot<<<(N_NODES * 32 + 255) / 256, 256>>>(As_[l], Ad_[l]);
        if (l < 2) {
            k_layer<<<(N_NODES * 32 + 255) / 256, 256>>>(bufs[l], batch, 0);
            cur = bufs[l];
        } else {
            k_layer<<<(N_NODES * 32 + 255) / 256, 256>>>(out, batch, 1);
        }
    }
}

// round 7
// speedup vs baseline: 1.6773x; 1.0659x over previous
#include <cuda_runtime.h>
#include <mma.h>
#include <cstdint>

using namespace nvcuda;

#define N_NODES 50000
#define NPAD    50048          // 391 * 128
#define N_EDGES 800000
#define E_TOT   (N_EDGES + N_NODES)
#define DIM     128
#define NUM_GRAPHS 512

// ---------------- scratch -------------------------------------------------
__device__ __align__(16) float g_x   [NPAD * DIM];   // padded copy of x (pad rows stay 0)
__device__ __align__(16) float g_buf0[NPAD * DIM];
__device__ __align__(16) float g_buf1[NPAD * DIM];
__device__ __align__(16) float g_h   [NPAD * DIM];
__device__ __align__(16) float g_asA [N_NODES];
__device__ __align__(16) float g_adA [N_NODES];
__device__ __align__(16) float g_asB [N_NODES];
__device__ __align__(16) float g_adB [N_NODES];
__device__ __align__(16) float g_vs  [3 * DIM];      // W^T a_src per layer
__device__ __align__(16) float g_vd  [3 * DIM];      // W^T a_dst per layer
__device__ __align__(16) int   g_src [E_TOT];
__device__ __align__(16) int   g_dst [E_TOT];
__device__ int   g_cnt [N_NODES];
__device__ int   g_cur [N_NODES];
__device__ int   g_row [N_NODES + 1];
__device__ int   g_csrs[E_TOT];

// ---------------- CSR build ----------------------------------------------
__global__ void k_zero_cnt() {
    int i = blockIdx.x * blockDim.x + threadIdx.x;
    if (i < N_NODES) g_cnt[i] = 0;
}

// 4 edges per thread, int4 loads, pipelined atomics
__global__ void k_prep_count(const int* __restrict__ ei) {
    int t = blockIdx.x * blockDim.x + threadIdx.x;
    int i0 = t * 4;
    if (i0 >= E_TOT) return;
    int4 s4, d4;
    if (i0 < N_EDGES) {                 // N_EDGES % 4 == 0 -> no straddle
        s4 = *(const int4*)(ei + i0);
        d4 = *(const int4*)(ei + N_EDGES + i0);
    } else {
        int n = i0 - N_EDGES;
        s4 = make_int4(n, n + 1, n + 2, n + 3);
        d4 = s4;
    }
    *(int4*)(g_src + i0) = s4;
    *(int4*)(g_dst + i0) = d4;
    atomicAdd(&g_cnt[d4.x], 1);
    atomicAdd(&g_cnt[d4.y], 1);
    atomicAdd(&g_cnt[d4.z], 1);
    atomicAdd(&g_cnt[d4.w], 1);
}

__global__ void k_scan() {          // single block, 1024 threads
    const int T = 1024;
    const int C = (N_NODES + T - 1) / T;
    __shared__ int ps[T];
    int t = threadIdx.x;
    int base = t * C;
    int s = 0;
    for (int i = 0; i < C; i++) { int n = base + i; if (n < N_NODES) s += g_cnt[n]; }
    ps[t] = s;
    __syncthreads();
    for (int off = 1; off < T; off <<= 1) {
        int v = (t >= off) ? ps[t - off] : 0;
        __syncthreads();
        ps[t] += v;
        __syncthreads();
    }
    int run = (t > 0) ? ps[t - 1] : 0;
    for (int i = 0; i < C; i++) {
        int n = base + i;
        if (n < N_NODES) { g_row[n] = run; g_cur[n] = run; run += g_cnt[n]; }
    }
    if (t == T - 1) g_row[N_NODES] = E_TOT;
}

__global__ void k_fill() {
    int t = blockIdx.x * blockDim.x + threadIdx.x;
    int i0 = t * 4;
    if (i0 >= E_TOT) return;
    int4 s4 = *(const int4*)(g_src + i0);
    int4 d4 = *(const int4*)(g_dst + i0);
    int p0 = atomicAdd(&g_cur[d4.x], 1);
    int p1 = atomicAdd(&g_cur[d4.y], 1);
    int p2 = atomicAdd(&g_cur[d4.z], 1);
    int p3 = atomicAdd(&g_cur[d4.w], 1);
    g_csrs[p0] = s4.x;
    g_csrs[p1] = s4.y;
    g_csrs[p2] = s4.z;
    g_csrs[p3] = s4.w;
}

// ---------------- v = W^T a (per layer, src+dst) --------------------------
// blockIdx.x = l*2 + (0:src,1:dst); 128 threads, thread k sums over j.
__global__ void k_matvec(const float* __restrict__ W0, const float* __restrict__ W1,
                         const float* __restrict__ W2,
                         const float* __restrict__ s0, const float* __restrict__ d0,
                         const float* __restrict__ s1, const float* __restrict__ d1,
                         const float* __restrict__ s2, const float* __restrict__ d2) {
    const float* W[3] = {W0, W1, W2};
    const float* A[6] = {s0, d0, s1, d1, s2, d2};
    int b = blockIdx.x;           // 0..5
    int l = b >> 1;
    const float* w = W[l];
    const float* a = A[b];
    int k = threadIdx.x;
    float s = 0.f;
#pragma unroll 4
    for (int j = 0; j < DIM; j++)
        s = fmaf(w[(size_t)j * DIM + k], a[j], s);
    if (b & 1) g_vd[l * DIM + k] = s;
    else       g_vs[l * DIM + k] = s;
}

// ---------------- copy x to padded buf + layer-0 attention dots -----------
__global__ void k_copy_x(const float* __restrict__ x) {
    int gt = blockIdx.x * blockDim.x + threadIdx.x;
    int n = gt >> 5, lane = gt & 31;
    if (n >= N_NODES) return;
    float4 v = ((const float4*)(x + (size_t)n * DIM))[lane];
    ((float4*)(g_x + (size_t)n * DIM))[lane] = v;
    float4 vs = ((const float4*)(g_vs))[lane];
    float4 vd = ((const float4*)(g_vd))[lane];
    float ps = v.x * vs.x + v.y * vs.y + v.z * vs.z + v.w * vs.w;
    float pd = v.x * vd.x + v.y * vd.y + v.z * vd.z + v.w * vd.w;
#pragma unroll
    for (int o = 16; o > 0; o >>= 1) {
        ps += __shfl_xor_sync(0xffffffffu, ps, o);
        pd += __shfl_xor_sync(0xffffffffu, pd, o);
    }
    if (lane == 0) { g_asA[n] = ps; g_adA[n] = pd; }
}

__global__ void k_zero(float* __restrict__ p, int n) {
    int i = blockIdx.x * blockDim.x + threadIdx.x;
    if (i < n) p[i] = 0.f;
}

// ---------------- tf32 tensor-core GEMM: H = act?(X) @ W^T ----------------
// smem-staged. 256 threads = 8 warps (4m x 2n); block 128x128, warp 32x64.
#define BKS  32
#define XPAD 36

__global__ void __launch_bounds__(256)
k_gemm(const float* __restrict__ X, const float* __restrict__ W,
       float* __restrict__ H, int apply_act) {
    __shared__ float Xs[128][XPAD];
    __shared__ float Ws[128][XPAD];
    int tid = threadIdx.x;
    int warp = tid >> 5;
    int wm = warp & 3, wn = warp >> 2;
    int n0 = blockIdx.x * 128;
    int fc = tid & 7;            // float4 col within 32-wide k slice
    int fr = tid >> 3;           // row 0..31

    wmma::fragment<wmma::accumulator, 16, 16, 8, float> c[2][4];
#pragma unroll
    for (int i = 0; i < 2; i++)
#pragma unroll
        for (int j = 0; j < 4; j++) wmma::fill_fragment(c[i][j], 0.f);

    for (int k0 = 0; k0 < DIM; k0 += BKS) {
#pragma unroll
        for (int it = 0; it < 4; it++) {
            int row = fr + it * 32;
            float4 v = *(const float4*)(X + (size_t)(n0 + row) * DIM + k0 + fc * 4);
            if (apply_act) {
                v.x = v.x > 0.f ? v.x : 0.01f * v.x;
                v.y = v.y > 0.f ? v.y : 0.01f * v.y;
                v.z = v.z > 0.f ? v.z : 0.01f * v.z;
                v.w = v.w > 0.f ? v.w : 0.01f * v.w;
            }
            v.x = wmma::__float_to_tf32(v.x);
            v.y = wmma::__float_to_tf32(v.y);
            v.z = wmma::__float_to_tf32(v.z);
            v.w = wmma::__float_to_tf32(v.w);
            *(float4*)&Xs[row][fc * 4] = v;

            float4 w = *(const float4*)(W + (size_t)row * DIM + k0 + fc * 4);
            w.x = wmma::__float_to_tf32(w.x);
            w.y = wmma::__float_to_tf32(w.y);
            w.z = wmma::__float_to_tf32(w.z);
            w.w = wmma::__float_to_tf32(w.w);
            *(float4*)&Ws[row][fc * 4] = w;
        }
        __syncthreads();

#pragma unroll
        for (int kk = 0; kk < BKS; kk += 8) {
            wmma::fragment<wmma::matrix_a, 16, 16, 8, wmma::precision::tf32, wmma::row_major> a[2];
            wmma::fragment<wmma::matrix_b, 16, 16, 8, wmma::precision::tf32, wmma::col_major> b[4];
#pragma unroll
            for (int i = 0; i < 2; i++)
                wmma::load_matrix_sync(a[i], &Xs[wm * 32 + i * 16][kk], XPAD);
#pragma unroll
            for (int j = 0; j < 4; j++)
                wmma::load_matrix_sync(b[j], &Ws[wn * 64 + j * 16][kk], XPAD);
#pragma unroll
            for (int i = 0; i < 2; i++)
#pragma unroll
                for (int j = 0; j < 4; j++)
                    wmma::mma_sync(c[i][j], a[i], b[j], c[i][j]);
        }
        __syncthreads();
    }

#pragma unroll
    for (int i = 0; i < 2; i++)
#pragma unroll
        for (int j = 0; j < 4; j++)
            wmma::store_matrix_sync(H + (size_t)(n0 + wm * 32 + i * 16) * DIM + wn * 64 + j * 16,
                                    c[i][j], DIM, wmma::mem_row_major);
}

// ---------------- fused softmax + aggregate + next-layer dots -------------
// one warp per dst node. mode 0: write node row + compute next-layer as/ad.
// mode 1: fused global_add_pool into outp (last layer).
__global__ void k_layer(float* __restrict__ outp, const int* __restrict__ batch,
                        const float* __restrict__ as_in, const float* __restrict__ ad_in,
                        float* __restrict__ as_out, float* __restrict__ ad_out,
                        const float* __restrict__ vs_n, const float* __restrict__ vd_n,
                        int act_next, int mode) {
    int gt = blockIdx.x * blockDim.x + threadIdx.x;
    int d = gt >> 5, lane = gt & 31;
    if (d >= N_NODES) return;
    int row0 = g_row[d], row1 = g_row[d + 1];
    float ad_d = ad_in[d];

    // pass 1: segment max (lanes split edges)
    float m = -1e30f;
    for (int i = row0 + lane; i < row1; i += 32) {
        float e = as_in[g_csrs[i]] + ad_d;
        e = e > 0.f ? e : 0.2f * e;
        m = fmaxf(m, e);
    }
#pragma unroll
    for (int o = 16; o > 0; o >>= 1)
        m = fmaxf(m, __shfl_xor_sync(0xffffffffu, m, o));

    // pass 2: z and weighted aggregate (lanes split dims)
    float z = 0.f;
    float4 acc = make_float4(0.f, 0.f, 0.f, 0.f);
    int i = row0;
    for (; i + 2 <= row1; i += 2) {
        int s0 = g_csrs[i], s1 = g_csrs[i + 1];
        float e0 = as_in[s0] + ad_d; e0 = e0 > 0.f ? e0 : 0.2f * e0;
        float e1 = as_in[s1] + ad_d; e1 = e1 > 0.f ? e1 : 0.2f * e1;
        float w0 = __expf(e0 - m), w1 = __expf(e1 - m);
        z += w0 + w1;
        float4 h0 = ((const float4*)(g_h + (size_t)s0 * DIM))[lane];
        float4 h1 = ((const float4*)(g_h + (size_t)s1 * DIM))[lane];
        acc.x = fmaf(w0, h0.x, fmaf(w1, h1.x, acc.x));
        acc.y = fmaf(w0, h0.y, fmaf(w1, h1.y, acc.y));
        acc.z = fmaf(w0, h0.z, fmaf(w1, h1.z, acc.z));
        acc.w = fmaf(w0, h0.w, fmaf(w1, h1.w, acc.w));
    }
    if (i < row1) {
        int s0 = g_csrs[i];
        float e0 = as_in[s0] + ad_d; e0 = e0 > 0.f ? e0 : 0.2f * e0;
        float w0 = __expf(e0 - m);
        z += w0;
        float4 h0 = ((const float4*)(g_h + (size_t)s0 * DIM))[lane];
        acc.x = fmaf(w0, h0.x, acc.x);
        acc.y = fmaf(w0, h0.y, acc.y);
        acc.z = fmaf(w0, h0.z, acc.z);
        acc.w = fmaf(w0, h0.w, acc.w);
    }
    float inv = 1.f / (z + 1e-16f);
    acc.x *= inv; acc.y *= inv; acc.z *= inv; acc.w *= inv;

    if (mode == 1) {
        float* p = outp + (size_t)batch[d] * DIM + lane * 4;
        asm volatile("red.global.add.v4.f32 [%0], {%1,%2,%3,%4};"
                     :: "l"(p), "f"(acc.x), "f"(acc.y), "f"(acc.z), "f"(acc.w) : "memory");
    } else {
        ((float4*)(outp + (size_t)d * DIM))[lane] = acc;
        // next-layer attention dots: (act?(acc)) . vs_n / vd_n
        float4 t = acc;
        if (act_next) {
            t.x = t.x > 0.f ? t.x : 0.01f * t.x;
            t.y = t.y > 0.f ? t.y : 0.01f * t.y;
            t.z = t.z > 0.f ? t.z : 0.01f * t.z;
            t.w = t.w > 0.f ? t.w : 0.01f * t.w;
        }
        float4 vs = ((const float4*)vs_n)[lane];
        float4 vd = ((const float4*)vd_n)[lane];
        float ps = t.x * vs.x + t.y * vs.y + t.z * vs.z + t.w * vs.w;
        float pd = t.x * vd.x + t.y * vd.y + t.z * vd.z + t.w * vd.w;
#pragma unroll
        for (int o = 16; o > 0; o >>= 1) {
            ps += __shfl_xor_sync(0xffffffffu, ps, o);
            pd += __shfl_xor_sync(0xffffffffu, pd, o);
        }
        if (lane == 0) { as_out[d] = ps; ad_out[d] = pd; }
    }
}

// ---------------- launch --------------------------------------------------
extern "C" void kernel_launch(void* const* d_in, const int* in_sizes, int n_in,
                              void* d_out, int out_size) {
    const float* x     = (const float*)d_in[0];
    const int*   ei    = (const int*)d_in[1];
    const int*   batch = (const int*)d_in[2];
    const float* W[3]   = {(const float*)d_in[3], (const float*)d_in[6], (const float*)d_in[9]};
    const float* As_[3] = {(const float*)d_in[4], (const float*)d_in[7], (const float*)d_in[10]};
    const float* Ad_[3] = {(const float*)d_in[5], (const float*)d_in[8], (const float*)d_in[11]};
    float* out = (float*)d_out;

    float *xp, *buf0, *buf1, *hp, *asA, *adA, *asB, *adB, *vsp, *vdp;
    cudaGetSymbolAddress((void**)&xp,   g_x);
    cudaGetSymbolAddress((void**)&buf0, g_buf0);
    cudaGetSymbolAddress((void**)&buf1, g_buf1);
    cudaGetSymbolAddress((void**)&hp,   g_h);
    cudaGetSymbolAddress((void**)&asA,  g_asA);
    cudaGetSymbolAddress((void**)&adA,  g_adA);
    cudaGetSymbolAddress((void**)&asB,  g_asB);
    cudaGetSymbolAddress((void**)&adB,  g_adB);
    cudaGetSymbolAddress((void**)&vsp,  g_vs);
    cudaGetSymbolAddress((void**)&vdp,  g_vd);

    // CSR build (per launch; capturable, no allocation)
    k_zero_cnt<<<(N_NODES + 255) / 256, 256>>>();
    k_prep_count<<<(E_TOT / 4 + 255) / 256, 256>>>(ei);
    k_scan<<<1, 1024>>>();
    k_fill<<<(E_TOT / 4 + 255) / 256, 256>>>();

    k_matvec<<<6, 128>>>(W[0], W[1], W[2], As_[0], Ad_[0], As_[1], Ad_[1], As_[2], Ad_[2]);
    k_copy_x<<<(N_NODES * 32 + 255) / 256, 256>>>(x);
    k_zero<<<(NUM_GRAPHS * DIM + 255) / 256, 256>>>(out, NUM_GRAPHS * DIM);

    // layer 0: reads as/ad set A, writes buf0 + set B (dots for layer 1, no act)
    k_gemm<<<NPAD / 128, 256>>>(xp, W[0], hp, 0);
    k_layer<<<(N_NODES * 32 + 255) / 256, 256>>>(buf0, batch, asA, adA, asB, adB,
                                                 vsp + DIM, vdp + DIM, 0, 0);
    // layer 1: reads set B, writes buf1 + set A (dots for layer 2, act=leaky0.01)
    k_gemm<<<NPAD / 128, 256>>>(buf0, W[1], hp, 0);
    k_layer<<<(N_NODES * 32 + 255) / 256, 256>>>(buf1, batch, asB, adB, asA, adA,
                                                 vsp + 2 * DIM, vdp + 2 * DIM, 1, 0);
    // layer 2: GEMM applies act to input; reads set A; fused pool into out
    k_gemm<<<NPAD / 128, 256>>>(buf1, W[2], hp, 1);
    k_layer<<<(N_NODES * 32 + 255) / 256, 256>>>(out, batch, asA, adA, nullptr, nullptr,
                                                 nullptr, nullptr, 0, 1);
}

// round 8
// speedup vs baseline: 2.0597x; 1.2281x over previous
#include <cuda_runtime.h>
#include <cuda_fp16.h>
#include <mma.h>
#include <cstdint>

using namespace nvcuda;

#define N_NODES 50000
#define NPAD    50048          // 391 * 128
#define N_EDGES 800000
#define E_TOT   (N_EDGES + N_NODES)
#define DIM     128
#define NUM_GRAPHS 512

// ---------------- scratch -------------------------------------------------
__device__ __align__(16) __half g_x  [NPAD * DIM];   // fp16 copy of x (pad rows stay 0)
__device__ __align__(16) __half g_b0 [NPAD * DIM];
__device__ __align__(16) __half g_b1 [NPAD * DIM];
__device__ __align__(16) __half g_hh [NPAD * DIM];   // GEMM output h (fp16)
__device__ __align__(16) float g_asA [N_NODES];
__device__ __align__(16) float g_adA [N_NODES];
__device__ __align__(16) float g_asB [N_NODES];
__device__ __align__(16) float g_adB [N_NODES];
__device__ __align__(16) float g_vs  [3 * DIM];      // W^T a_src per layer
__device__ __align__(16) float g_vd  [3 * DIM];      // W^T a_dst per layer
__device__ __align__(16) int   g_src [E_TOT];
__device__ __align__(16) int   g_dst [E_TOT];
__device__ __align__(16) int   g_rank[E_TOT];
__device__ int   g_cnt [N_NODES];
__device__ int   g_row [N_NODES + 1];
__device__ int   g_csrs[E_TOT];

// ---------------- CSR build ----------------------------------------------
__global__ void k_zero_cnt() {
    int i = blockIdx.x * blockDim.x + threadIdx.x;
    if (i < N_NODES) g_cnt[i] = 0;
}

// 4 edges per thread; atomicAdd return = rank of edge within its dst segment
__global__ void k_prep_count(const int* __restrict__ ei) {
    int t = blockIdx.x * blockDim.x + threadIdx.x;
    int i0 = t * 4;
    if (i0 >= E_TOT) return;
    int4 s4, d4;
    if (i0 < N_EDGES) {                 // N_EDGES % 4 == 0 -> no straddle
        s4 = *(const int4*)(ei + i0);
        d4 = *(const int4*)(ei + N_EDGES + i0);
    } else {
        int n = i0 - N_EDGES;
        s4 = make_int4(n, n + 1, n + 2, n + 3);
        d4 = s4;
    }
    *(int4*)(g_src + i0) = s4;
    *(int4*)(g_dst + i0) = d4;
    int4 r4;
    r4.x = atomicAdd(&g_cnt[d4.x], 1);
    r4.y = atomicAdd(&g_cnt[d4.y], 1);
    r4.z = atomicAdd(&g_cnt[d4.z], 1);
    r4.w = atomicAdd(&g_cnt[d4.w], 1);
    *(int4*)(g_rank + i0) = r4;
}

__global__ void k_scan() {          // single block, 1024 threads
    const int T = 1024;
    const int C = (N_NODES + T - 1) / T;
    __shared__ int ps[T];
    int t = threadIdx.x;
    int base = t * C;
    int s = 0;
    for (int i = 0; i < C; i++) { int n = base + i; if (n < N_NODES) s += g_cnt[n]; }
    ps[t] = s;
    __syncthreads();
    for (int off = 1; off < T; off <<= 1) {
        int v = (t >= off) ? ps[t - off] : 0;
        __syncthreads();
        ps[t] += v;
        __syncthreads();
    }
    int run = (t > 0) ? ps[t - 1] : 0;
    for (int i = 0; i < C; i++) {
        int n = base + i;
        if (n < N_NODES) { g_row[n] = run; run += g_cnt[n]; }
    }
    if (t == T - 1) g_row[N_NODES] = E_TOT;
}

// atomic-free fill: pos = row[d] + rank
__global__ void k_fill() {
    int t = blockIdx.x * blockDim.x + threadIdx.x;
    int i0 = t * 4;
    if (i0 >= E_TOT) return;
    int4 s4 = *(const int4*)(g_src + i0);
    int4 d4 = *(const int4*)(g_dst + i0);
    int4 r4 = *(const int4*)(g_rank + i0);
    g_csrs[g_row[d4.x] + r4.x] = s4.x;
    g_csrs[g_row[d4.y] + r4.y] = s4.y;
    g_csrs[g_row[d4.z] + r4.z] = s4.z;
    g_csrs[g_row[d4.w] + r4.w] = s4.w;
}

// ---------------- v = W^T a (per layer, src+dst) --------------------------
__global__ void k_matvec(const float* __restrict__ W0, const float* __restrict__ W1,
                         const float* __restrict__ W2,
                         const float* __restrict__ s0, const float* __restrict__ d0,
                         const float* __restrict__ s1, const float* __restrict__ d1,
                         const float* __restrict__ s2, const float* __restrict__ d2) {
    const float* W[3] = {W0, W1, W2};
    const float* A[6] = {s0, d0, s1, d1, s2, d2};
    int b = blockIdx.x;           // 0..5
    int l = b >> 1;
    const float* w = W[l];
    const float* a = A[b];
    int k = threadIdx.x;
    float s = 0.f;
#pragma unroll 4
    for (int j = 0; j < DIM; j++)
        s = fmaf(w[(size_t)j * DIM + k], a[j], s);
    if (b & 1) g_vd[l * DIM + k] = s;
    else       g_vs[l * DIM + k] = s;
}

// ---------------- copy x to fp16 padded buf + layer-0 attention dots ------
__global__ void k_copy_x(const float* __restrict__ x) {
    int gt = blockIdx.x * blockDim.x + threadIdx.x;
    int n = gt >> 5, lane = gt & 31;
    if (n >= N_NODES) return;
    float4 v = ((const float4*)(x + (size_t)n * DIM))[lane];
    __half2 h0 = __floats2half2_rn(v.x, v.y);
    __half2 h1 = __floats2half2_rn(v.z, v.w);
    uint2 u;
    u.x = *(unsigned*)&h0;
    u.y = *(unsigned*)&h1;
    ((uint2*)(g_x + (size_t)n * DIM))[lane] = u;
    float4 vs = ((const float4*)(g_vs))[lane];
    float4 vd = ((const float4*)(g_vd))[lane];
    float ps = v.x * vs.x + v.y * vs.y + v.z * vs.z + v.w * vs.w;
    float pd = v.x * vd.x + v.y * vd.y + v.z * vd.z + v.w * vd.w;
#pragma unroll
    for (int o = 16; o > 0; o >>= 1) {
        ps += __shfl_xor_sync(0xffffffffu, ps, o);
        pd += __shfl_xor_sync(0xffffffffu, pd, o);
    }
    if (lane == 0) { g_asA[n] = ps; g_adA[n] = pd; }
}

__global__ void k_zero(float* __restrict__ p, int n) {
    int i = blockIdx.x * blockDim.x + threadIdx.x;
    if (i < n) p[i] = 0.f;
}

// ---------------- fp16 tensor-core GEMM: H = act?(X) @ W^T ----------------
// X fp16 [NPAD,128], W fp32 [128,128], H fp16. 256 thr = 8 warps (4m x 2n).
// Block tile 128x128, warp tile 32x64, smem-staged, BK=32.
#define XPADH 48            // half elements per smem row (96B, 16B-aligned)
#define GEMM_SMEM 65536     // epilogue: 8 warps * 32*64 fp32

__global__ void __launch_bounds__(256)
k_gemm(const __half* __restrict__ X, const float* __restrict__ W,
       __half* __restrict__ H, int apply_act) {
    extern __shared__ __align__(16) char smem[];
    __half* Xs = (__half*)smem;                       // [128][XPADH]
    __half* Ws = (__half*)smem + 128 * XPADH;         // [128][XPADH]
    int tid = threadIdx.x;
    int warp = tid >> 5, lane = tid & 31;
    int wm = warp & 3, wn = warp >> 2;
    int n0 = blockIdx.x * 128;

    wmma::fragment<wmma::accumulator, 16, 16, 16, float> c[2][4];
#pragma unroll
    for (int i = 0; i < 2; i++)
#pragma unroll
        for (int j = 0; j < 4; j++) wmma::fill_fragment(c[i][j], 0.f);

    for (int k0 = 0; k0 < DIM; k0 += 32) {
        // stage X: 128 rows x 32 halves; 2 x uint4 (8 halves) per thread
#pragma unroll
        for (int it = 0; it < 2; it++) {
            int u = tid + it * 256;
            int row = u >> 2, c8 = (u & 3) * 8;
            uint4 v = *(const uint4*)(X + (size_t)(n0 + row) * DIM + k0 + c8);
            if (apply_act) {
                __half2* hp = (__half2*)&v;
#pragma unroll
                for (int q = 0; q < 4; q++) {
                    float2 f = __half22float2(hp[q]);
                    f.x = f.x > 0.f ? f.x : 0.01f * f.x;
                    f.y = f.y > 0.f ? f.y : 0.01f * f.y;
                    hp[q] = __floats2half2_rn(f.x, f.y);
                }
            }
            *(uint4*)(Xs + row * XPADH + c8) = v;
        }
        // stage W (fp32 -> fp16): 128 rows x 32 floats; 4 x float4 per thread
#pragma unroll
        for (int it = 0; it < 4; it++) {
            int u = tid + it * 256;
            int row = u >> 3, c4 = (u & 7) * 4;
            float4 w = *(const float4*)(W + (size_t)row * DIM + k0 + c4);
            __half2 w0 = __floats2half2_rn(w.x, w.y);
            __half2 w1 = __floats2half2_rn(w.z, w.w);
            uint2 uu;
            uu.x = *(unsigned*)&w0;
            uu.y = *(unsigned*)&w1;
            *(uint2*)(Ws + row * XPADH + c4) = uu;
        }
        __syncthreads();

#pragma unroll
        for (int kk = 0; kk < 32; kk += 16) {
            wmma::fragment<wmma::matrix_a, 16, 16, 16, __half, wmma::row_major> a[2];
            wmma::fragment<wmma::matrix_b, 16, 16, 16, __half, wmma::col_major> b[4];
#pragma unroll
            for (int i = 0; i < 2; i++)
                wmma::load_matrix_sync(a[i], Xs + (wm * 32 + i * 16) * XPADH + kk, XPADH);
#pragma unroll
            for (int j = 0; j < 4; j++)
                wmma::load_matrix_sync(b[j], Ws + (wn * 64 + j * 16) * XPADH + kk, XPADH);
#pragma unroll
            for (int i = 0; i < 2; i++)
#pragma unroll
                for (int j = 0; j < 4; j++)
                    wmma::mma_sync(c[i][j], a[i], b[j], c[i][j]);
        }
        __syncthreads();
    }

    // epilogue: per-warp smem region 32x64 fp32, convert to fp16, store
    float* epi = (float*)smem + warp * (32 * 64);
#pragma unroll
    for (int i = 0; i < 2; i++)
#pragma unroll
        for (int j = 0; j < 4; j++)
            wmma::store_matrix_sync(epi + i * 16 * 64 + j * 16, c[i][j], 64, wmma::mem_row_major);
    __syncwarp();
    {
        int row = lane;
        __half* hout = H + (size_t)(n0 + wm * 32 + row) * DIM + wn * 64;
        const float* src = epi + row * 64;
#pragma unroll
        for (int c0 = 0; c0 < 64; c0 += 8) {
            float4 f0 = *(const float4*)(src + c0);
            float4 f1 = *(const float4*)(src + c0 + 4);
            __half2 a0 = __floats2half2_rn(f0.x, f0.y);
            __half2 a1 = __floats2half2_rn(f0.z, f0.w);
            __half2 a2 = __floats2half2_rn(f1.x, f1.y);
            __half2 a3 = __floats2half2_rn(f1.z, f1.w);
            uint4 u;
            u.x = *(unsigned*)&a0; u.y = *(unsigned*)&a1;
            u.z = *(unsigned*)&a2; u.w = *(unsigned*)&a3;
            *(uint4*)(hout + c0) = u;
        }
    }
}

// ---------------- fused softmax + aggregate + next-layer dots -------------
// one warp per dst node; lane covers dims [4*lane, 4*lane+4).
__global__ void k_layer(void* __restrict__ outp, const int* __restrict__ batch,
                        const float* __restrict__ as_in, const float* __restrict__ ad_in,
                        float* __restrict__ as_out, float* __restrict__ ad_out,
                        const float* __restrict__ vs_n, const float* __restrict__ vd_n,
                        int act_next, int mode) {
    int gt = blockIdx.x * blockDim.x + threadIdx.x;
    int d = gt >> 5, lane = gt & 31;
    if (d >= N_NODES) return;
    int row0 = g_row[d], row1 = g_row[d + 1];
    float ad_d = ad_in[d];

    // pass 1: segment max (lanes split edges)
    float m = -1e30f;
    for (int i = row0 + lane; i < row1; i += 32) {
        float e = as_in[g_csrs[i]] + ad_d;
        e = e > 0.f ? e : 0.2f * e;
        m = fmaxf(m, e);
    }
#pragma unroll
    for (int o = 16; o > 0; o >>= 1)
        m = fmaxf(m, __shfl_xor_sync(0xffffffffu, m, o));

    // pass 2: z and weighted aggregate (fp16 gather, fp32 math)
    float z = 0.f;
    float4 acc = make_float4(0.f, 0.f, 0.f, 0.f);
    int i = row0;
    for (; i + 2 <= row1; i += 2) {
        int s0 = g_csrs[i], s1 = g_csrs[i + 1];
        float e0 = as_in[s0] + ad_d; e0 = e0 > 0.f ? e0 : 0.2f * e0;
        float e1 = as_in[s1] + ad_d; e1 = e1 > 0.f ? e1 : 0.2f * e1;
        float w0 = __expf(e0 - m), w1 = __expf(e1 - m);
        z += w0 + w1;
        uint2 u0 = ((const uint2*)(g_hh + (size_t)s0 * DIM))[lane];
        uint2 u1 = ((const uint2*)(g_hh + (size_t)s1 * DIM))[lane];
        float2 a0 = __half22float2(*(__half2*)&u0.x);
        float2 b0 = __half22float2(*(__half2*)&u0.y);
        float2 a1 = __half22float2(*(__half2*)&u1.x);
        float2 b1 = __half22float2(*(__half2*)&u1.y);
        acc.x = fmaf(w0, a0.x, fmaf(w1, a1.x, acc.x));
        acc.y = fmaf(w0, a0.y, fmaf(w1, a1.y, acc.y));
        acc.z = fmaf(w0, b0.x, fmaf(w1, b1.x, acc.z));
        acc.w = fmaf(w0, b0.y, fmaf(w1, b1.y, acc.w));
    }
    if (i < row1) {
        int s0 = g_csrs[i];
        float e0 = as_in[s0] + ad_d; e0 = e0 > 0.f ? e0 : 0.2f * e0;
        float w0 = __expf(e0 - m);
        z += w0;
        uint2 u0 = ((const uint2*)(g_hh + (size_t)s0 * DIM))[lane];
        float2 a0 = __half22float2(*(__half2*)&u0.x);
        float2 b0 = __half22float2(*(__half2*)&u0.y);
        acc.x = fmaf(w0, a0.x, acc.x);
        acc.y = fmaf(w0, a0.y, acc.y);
        acc.z = fmaf(w0, b0.x, acc.z);
        acc.w = fmaf(w0, b0.y, acc.w);
    }
    float inv = 1.f / (z + 1e-16f);
    acc.x *= inv; acc.y *= inv; acc.z *= inv; acc.w *= inv;

    if (mode == 1) {
        float* p = (float*)outp + (size_t)batch[d] * DIM + lane * 4;
        asm volatile("red.global.add.v4.f32 [%0], {%1,%2,%3,%4};"
                     :: "l"(p), "f"(acc.x), "f"(acc.y), "f"(acc.z), "f"(acc.w) : "memory");
    } else {
        __half2 h0 = __floats2half2_rn(acc.x, acc.y);
        __half2 h1 = __floats2half2_rn(acc.z, acc.w);
        uint2 u;
        u.x = *(unsigned*)&h0;
        u.y = *(unsigned*)&h1;
        ((uint2*)((__half*)outp + (size_t)d * DIM))[lane] = u;
        // next-layer attention dots from fp32 acc
        float4 t = acc;
        if (act_next) {
            t.x = t.x > 0.f ? t.x : 0.01f * t.x;
            t.y = t.y > 0.f ? t.y : 0.01f * t.y;
            t.z = t.z > 0.f ? t.z : 0.01f * t.z;
            t.w = t.w > 0.f ? t.w : 0.01f * t.w;
        }
        float4 vs = ((const float4*)vs_n)[lane];
        float4 vd = ((const float4*)vd_n)[lane];
        float ps = t.x * vs.x + t.y * vs.y + t.z * vs.z + t.w * vs.w;
        float pd = t.x * vd.x + t.y * vd.y + t.z * vd.z + t.w * vd.w;
#pragma unroll
        for (int o = 16; o > 0; o >>= 1) {
            ps += __shfl_xor_sync(0xffffffffu, ps, o);
            pd += __shfl_xor_sync(0xffffffffu, pd, o);
        }
        if (lane == 0) { as_out[d] = ps; ad_out[d] = pd; }
    }
}

// ---------------- launch --------------------------------------------------
extern "C" void kernel_launch(void* const* d_in, const int* in_sizes, int n_in,
                              void* d_out, int out_size) {
    const float* x     = (const float*)d_in[0];
    const int*   ei    = (const int*)d_in[1];
    const int*   batch = (const int*)d_in[2];
    const float* W[3]   = {(const float*)d_in[3], (const float*)d_in[6], (const float*)d_in[9]};
    const float* As_[3] = {(const float*)d_in[4], (const float*)d_in[7], (const float*)d_in[10]};
    const float* Ad_[3] = {(const float*)d_in[5], (const float*)d_in[8], (const float*)d_in[11]};
    float* out = (float*)d_out;

    __half *xp, *b0, *b1, *hp;
    float *asA, *adA, *asB, *adB, *vsp, *vdp;
    cudaGetSymbolAddress((void**)&xp,  g_x);
    cudaGetSymbolAddress((void**)&b0,  g_b0);
    cudaGetSymbolAddress((void**)&b1,  g_b1);
    cudaGetSymbolAddress((void**)&hp,  g_hh);
    cudaGetSymbolAddress((void**)&asA, g_asA);
    cudaGetSymbolAddress((void**)&adA, g_adA);
    cudaGetSymbolAddress((void**)&asB, g_asB);
    cudaGetSymbolAddress((void**)&adB, g_adB);
    cudaGetSymbolAddress((void**)&vsp, g_vs);
    cudaGetSymbolAddress((void**)&vdp, g_vd);

    cudaFuncSetAttribute(k_gemm, cudaFuncAttributeMaxDynamicSharedMemorySize, GEMM_SMEM);

    // CSR build (per launch; capturable, no allocation)
    k_zero_cnt<<<(N_NODES + 255) / 256, 256>>>();
    k_prep_count<<<(E_TOT / 4 + 255) / 256, 256>>>(ei);
    k_scan<<<1, 1024>>>();
    k_fill<<<(E_TOT / 4 + 255) / 256, 256>>>();

    k_matvec<<<6, 128>>>(W[0], W[1], W[2], As_[0], Ad_[0], As_[1], Ad_[1], As_[2], Ad_[2]);
    k_copy_x<<<(N_NODES * 32 + 255) / 256, 256>>>(x);
    k_zero<<<(NUM_GRAPHS * DIM + 255) / 256, 256>>>(out, NUM_GRAPHS * DIM);

    // layer 0: dots set A -> writes b0 + set B (dots for layer 1, no act)
    k_gemm<<<NPAD / 128, 256, GEMM_SMEM>>>(xp, W[0], hp, 0);
    k_layer<<<(N_NODES * 32 + 255) / 256, 256>>>(b0, batch, asA, adA, asB, adB,
                                                 vsp + DIM, vdp + DIM, 0, 0);
    // layer 1: reads set B -> writes b1 + set A (dots for layer 2, act=leaky0.01)
    k_gemm<<<NPAD / 128, 256, GEMM_SMEM>>>(b0, W[1], hp, 0);
    k_layer<<<(N_NODES * 32 + 255) / 256, 256>>>(b1, batch, asB, adB, asA, adA,
                                                 vsp + 2 * DIM, vdp + 2 * DIM, 1, 0);
    // layer 2: GEMM applies act to input; reads set A; fused pool into out
    k_gemm<<<NPAD / 128, 256, GEMM_SMEM>>>(b1, W[2], hp, 1);
    k_layer<<<(N_NODES * 32 + 255) / 256, 256>>>(out, batch, asA, adA, nullptr, nullptr,
                                                 nullptr, nullptr, 0, 1);
}